// round 1
// baseline (speedup 1.0000x reference)
#include <cuda_runtime.h>

#define H     1024
#define HH    (H * H)
#define P     (3 * HH)
#define P4    (P / 4)
#define HH4   (HH / 4)
#define NBINS 256
#define NIDX  400000

// ---------------- device scratch (no allocation allowed) ----------------
__device__ int    g_hist[6 * NBINS];  // [0..2]=dst(ref_masked) hist, [3..5]=ref(target_masked) hist
__device__ float  g_tab[3][NBINS];    // table[b]/255 per channel
__device__ double g_acc;

__device__ __forceinline__ float dn(float x) {
    float v = (x + 1.0f) * 0.5f;
    return fminf(fmaxf(v, 0.0f), 1.0f);
}

// ---------------- kernel 1: zero scratch (graph-replay deterministic) ----
__global__ void init_k() {
    int t = blockIdx.x * blockDim.x + threadIdx.x;
    for (int i = t; i < 6 * NBINS; i += blockDim.x * gridDim.x) g_hist[i] = 0;
    if (t == 0) g_acc = 0.0;
}

// ---------------- kernel 2: elementwise transforms, float4-vectorized ----
// out layout: [0:P) target_masked/255, [P:2P) ref_masked/255,
//             [2P:3P) input_masked/255, [3P:4P) input_match/255 (base = ref_masked/255)
__global__ void ew_k(const float4* __restrict__ inp, const float4* __restrict__ tgt,
                     const float4* __restrict__ ref, const float4* __restrict__ msrc,
                     const float4* __restrict__ mtar, float4* __restrict__ out) {
    int i = blockIdx.x * blockDim.x + threadIdx.x;
    if (i >= P4) return;
    int p = i & (HH4 - 1);
    float4 ms = msrc[p];
    float4 mt = mtar[p];
    float4 t = tgt[i], r = ref[i], in = inp[i];
    float4 otm, orm, oim;
#define DO_C(f)                                                        \
    {                                                                  \
        float mu = (ms.f != 0.0f) ? 1.0f : 0.0f;                       \
        float tu = (mt.f != 0.0f) ? 1.0f : 0.0f;                       \
        otm.f = dn(t.f) * tu;                                          \
        orm.f = dn(r.f) * mu;                                          \
        oim.f = fminf(fmaxf(in.f, 0.0f), 1.0f) * mu;                   \
    }
    DO_C(x) DO_C(y) DO_C(z) DO_C(w)
#undef DO_C
    out[i]          = otm;
    out[P4 + i]     = orm;
    out[2 * P4 + i] = oim;
    out[3 * P4 + i] = orm;   // input_match base; scatter overwrites selected pixels
}

// ---------------- kernel 3: privatized histograms ------------------------
__global__ void hist_k(const float* __restrict__ ref, const float* __restrict__ tgt,
                       const float* __restrict__ msrc, const float* __restrict__ mtar,
                       const int* __restrict__ i0, const int* __restrict__ i1,
                       const int* __restrict__ i2, const int* __restrict__ i3) {
    __shared__ int sh[6 * NBINS];
    for (int t = threadIdx.x; t < 6 * NBINS; t += blockDim.x) sh[t] = 0;
    __syncthreads();

    int k = blockIdx.x * blockDim.x + threadIdx.x;
    if (k < NIDX) {
        int pd = i0[k] * H + i1[k];
        bool dz = (msrc[pd] == 0.0f);
#pragma unroll
        for (int c = 0; c < 3; c++) {
            float v = dz ? 0.0f : dn(ref[c * HH + pd]) * 255.0f;
            int b = min((int)v, NBINS - 1);
            atomicAdd(&sh[c * NBINS + b], 1);
        }
        int pr = i2[k] * H + i3[k];
        bool tz = (mtar[pr] == 0.0f);
#pragma unroll
        for (int c = 0; c < 3; c++) {
            float v = tz ? 0.0f : dn(tgt[c * HH + pr]) * 255.0f;
            int b = min((int)v, NBINS - 1);
            atomicAdd(&sh[(3 + c) * NBINS + b], 1);
        }
    }
    __syncthreads();
    for (int t = threadIdx.x; t < 6 * NBINS; t += blockDim.x) {
        int v = sh[t];
        if (v) atomicAdd(&g_hist[t], v);
    }
}

// ---------------- kernel 4: CDF + transfer table (1 block, tiny) ---------
__global__ void tab_k() {
    __shared__ float cdfd[3][NBINS];
    __shared__ float cdfr[3][NBINS];
    int b = threadIdx.x;  // 256 threads
    if (b < 6) {
        int c = b;
        float run = 0.0f;
        for (int i = 0; i < NBINS; i++) {
            run += (float)g_hist[c * NBINS + i];
            if (c < 3) cdfd[c][i] = run;
            else       cdfr[c - 3][i] = run;
        }
    }
    __syncthreads();
    // normalize with IEEE division to bit-match JAX (comparisons below are exact)
#pragma unroll
    for (int c = 0; c < 3; c++) {
        cdfd[c][b] = __fdiv_rn(cdfd[c][b], (float)NIDX);
        cdfr[c][b] = __fdiv_rn(cdfr[c][b], (float)NIDX);
    }
    __syncthreads();
#pragma unroll
    for (int c = 0; c < 3; c++) {
        int tab;
        if (b == NBINS - 1) {
            tab = NBINS - 1;
        } else {
            tab = b;
            float r = cdfd[c][b];
            for (int j = 0; j < NBINS - 1; j++) {
                if (r >= cdfr[c][j] && r <= cdfr[c][j + 1]) { tab = j + 1; break; }
            }
        }
        g_tab[c][b] = __fdiv_rn((float)tab, 255.0f);
    }
}

// ---------------- kernel 5: scatter matched values ------------------------
__global__ void scat_k(const float* __restrict__ ref, const float* __restrict__ msrc,
                       const int* __restrict__ i0, const int* __restrict__ i1,
                       float* __restrict__ o_match) {
    int k = blockIdx.x * blockDim.x + threadIdx.x;
    if (k >= NIDX) return;
    int pd = i0[k] * H + i1[k];
    bool dz = (msrc[pd] == 0.0f);
#pragma unroll
    for (int c = 0; c < 3; c++) {
        float v = dz ? 0.0f : dn(ref[c * HH + pd]) * 255.0f;
        int b = min((int)v, NBINS - 1);
        o_match[c * HH + pd] = g_tab[c][b];  // duplicates write identical values
    }
}

// ---------------- kernel 6: L1 mean reduction -----------------------------
__global__ void loss_k(const float4* __restrict__ a, const float4* __restrict__ b) {
    float local = 0.0f;
    for (int i = blockIdx.x * blockDim.x + threadIdx.x; i < P4;
         i += gridDim.x * blockDim.x) {
        float4 x = a[i], y = b[i];
        local += fabsf(x.x - y.x) + fabsf(x.y - y.y) +
                 fabsf(x.z - y.z) + fabsf(x.w - y.w);
    }
#pragma unroll
    for (int off = 16; off; off >>= 1) local += __shfl_down_sync(0xFFFFFFFFu, local, off);
    __shared__ float ws[8];
    if ((threadIdx.x & 31) == 0) ws[threadIdx.x >> 5] = local;
    __syncthreads();
    if (threadIdx.x < 32) {
        float v = (threadIdx.x < (blockDim.x >> 5)) ? ws[threadIdx.x] : 0.0f;
#pragma unroll
        for (int off = 4; off; off >>= 1) v += __shfl_down_sync(0xFFFFFFFFu, v, off);
        if (threadIdx.x == 0) atomicAdd(&g_acc, (double)v);
    }
}

__global__ void fin_k(float* __restrict__ o) {
    o[0] = (float)(g_acc / (double)P);
}

// ---------------- launch -------------------------------------------------
extern "C" void kernel_launch(void* const* d_in, const int* in_sizes, int n_in,
                              void* d_out, int out_size) {
    const float* inp  = (const float*)d_in[0];
    const float* tgt  = (const float*)d_in[1];
    const float* ref  = (const float*)d_in[2];
    const float* msrc = (const float*)d_in[3];
    const float* mtar = (const float*)d_in[4];
    // d_in[5] = target_data_eye (unused by reference)
    const int* i0 = (const int*)d_in[6];
    const int* i1 = (const int*)d_in[7];
    const int* i2 = (const int*)d_in[8];
    const int* i3 = (const int*)d_in[9];
    float* out = (float*)d_out;

    init_k<<<2, 256>>>();
    ew_k<<<(P4 + 255) / 256, 256>>>((const float4*)inp, (const float4*)tgt,
                                    (const float4*)ref, (const float4*)msrc,
                                    (const float4*)mtar, (float4*)out);
    hist_k<<<(NIDX + 255) / 256, 256>>>(ref, tgt, msrc, mtar, i0, i1, i2, i3);
    tab_k<<<1, 256>>>();
    scat_k<<<(NIDX + 255) / 256, 256>>>(ref, msrc, i0, i1, out + (size_t)3 * P);
    loss_k<<<148 * 4, 256>>>((const float4*)(out + (size_t)2 * P),
                             (const float4*)(out + (size_t)3 * P));
    fin_k<<<1, 1>>>(out + (size_t)4 * P);
}

// round 2
// speedup vs baseline: 1.1068x; 1.1068x over previous
#include <cuda_runtime.h>

#define H     1024
#define HH    (H * H)
#define P     (3 * HH)
#define P4    (P / 4)
#define HH4   (HH / 4)
#define NBINS 256
#define NIDX  400000

// ---------------- device scratch (no allocation allowed) ----------------
__device__ int    g_hist[6 * NBINS];  // [0..2]=dst(ref_masked) hist, [3..5]=ref(target_masked) hist
__device__ float  g_tab[3][NBINS];    // table[b]/255 per channel
__device__ double g_acc;

__device__ __forceinline__ float dn(float x) {
    float v = (x + 1.0f) * 0.5f;
    return fminf(fmaxf(v, 0.0f), 1.0f);
}

// ---------------- kernel 1: elementwise transforms (+ scratch zeroing) ----
// out layout: [0:P) target_masked/255, [P:2P) ref_masked/255,
//             [2P:3P) input_masked/255, [3P:4P) input_match/255 (base = ref_masked/255)
__global__ void ew_k(const float4* __restrict__ inp, const float4* __restrict__ tgt,
                     const float4* __restrict__ ref, const float4* __restrict__ msrc,
                     const float4* __restrict__ mtar, float4* __restrict__ out) {
    // block 0 also zeros the scratch (completes before hist_k by stream order)
    if (blockIdx.x == 0) {
        for (int t = threadIdx.x; t < 6 * NBINS; t += blockDim.x) g_hist[t] = 0;
        if (threadIdx.x == 0) g_acc = 0.0;
    }
    int i = blockIdx.x * blockDim.x + threadIdx.x;
    if (i >= P4) return;
    int p = i & (HH4 - 1);
    float4 ms = msrc[p];
    float4 mt = mtar[p];
    float4 t = tgt[i], r = ref[i], in = inp[i];
    float4 otm, orm, oim;
#define DO_C(f)                                                        \
    {                                                                  \
        float mu = (ms.f != 0.0f) ? 1.0f : 0.0f;                       \
        float tu = (mt.f != 0.0f) ? 1.0f : 0.0f;                       \
        otm.f = dn(t.f) * tu;                                          \
        orm.f = dn(r.f) * mu;                                          \
        oim.f = fminf(fmaxf(in.f, 0.0f), 1.0f) * mu;                   \
    }
    DO_C(x) DO_C(y) DO_C(z) DO_C(w)
#undef DO_C
    out[i]          = otm;
    out[P4 + i]     = orm;
    out[2 * P4 + i] = oim;
    out[3 * P4 + i] = orm;   // input_match base; scatter overwrites selected pixels
}

// ---------------- kernel 2: privatized histograms ------------------------
__global__ void hist_k(const float* __restrict__ ref, const float* __restrict__ tgt,
                       const float* __restrict__ msrc, const float* __restrict__ mtar,
                       const int* __restrict__ i0, const int* __restrict__ i1,
                       const int* __restrict__ i2, const int* __restrict__ i3) {
    __shared__ int sh[6 * NBINS];
    for (int t = threadIdx.x; t < 6 * NBINS; t += blockDim.x) sh[t] = 0;
    __syncthreads();

    int k = blockIdx.x * blockDim.x + threadIdx.x;
    if (k < NIDX) {
        int pd = i0[k] * H + i1[k];
        bool dz = (msrc[pd] == 0.0f);
#pragma unroll
        for (int c = 0; c < 3; c++) {
            float v = dz ? 0.0f : dn(ref[c * HH + pd]) * 255.0f;
            int b = min((int)v, NBINS - 1);
            atomicAdd(&sh[c * NBINS + b], 1);
        }
        int pr = i2[k] * H + i3[k];
        bool tz = (mtar[pr] == 0.0f);
#pragma unroll
        for (int c = 0; c < 3; c++) {
            float v = tz ? 0.0f : dn(tgt[c * HH + pr]) * 255.0f;
            int b = min((int)v, NBINS - 1);
            atomicAdd(&sh[(3 + c) * NBINS + b], 1);
        }
    }
    __syncthreads();
    for (int t = threadIdx.x; t < 6 * NBINS; t += blockDim.x) {
        int v = sh[t];
        if (v) atomicAdd(&g_hist[t], v);
    }
}

// ---------------- kernel 3: CDF + transfer table (1 block, 256 thr) ------
// Cumsum via Hillis-Steele block scan in shared memory. Counts are integers
// <= 400000 < 2^24, so every partial sum is exactly representable in f32 and
// any summation order bit-matches JAX's sequential cumsum.
__global__ void tab_k() {
    __shared__ float cdf[6][NBINS];   // [0..2]=dst, [3..5]=ref
    int b = threadIdx.x;              // 256 threads

    // coalesced load of all 6 histograms
#pragma unroll
    for (int c = 0; c < 6; c++) cdf[c][b] = (float)g_hist[c * NBINS + b];
    __syncthreads();

    // inclusive scan, all 6 channels per step
    for (int off = 1; off < NBINS; off <<= 1) {
        float v[6];
#pragma unroll
        for (int c = 0; c < 6; c++) v[c] = (b >= off) ? cdf[c][b - off] : 0.0f;
        __syncthreads();
#pragma unroll
        for (int c = 0; c < 6; c++) cdf[c][b] += v[c];
        __syncthreads();
    }

    // normalize with IEEE division (cdf[-1] == NIDX exactly)
#pragma unroll
    for (int c = 0; c < 6; c++) cdf[c][b] = __fdiv_rn(cdf[c][b], (float)NIDX);
    __syncthreads();

#pragma unroll
    for (int c = 0; c < 3; c++) {
        int tab;
        if (b == NBINS - 1) {
            tab = NBINS - 1;
        } else {
            tab = b;
            float r = cdf[c][b];
            const float* cr = cdf[3 + c];
            for (int j = 0; j < NBINS - 1; j++) {
                if (r >= cr[j] && r <= cr[j + 1]) { tab = j + 1; break; }
            }
        }
        g_tab[c][b] = __fdiv_rn((float)tab, 255.0f);
    }
}

// ---------------- kernel 4: scatter matched values ------------------------
__global__ void scat_k(const float* __restrict__ ref, const float* __restrict__ msrc,
                       const int* __restrict__ i0, const int* __restrict__ i1,
                       float* __restrict__ o_match) {
    int k = blockIdx.x * blockDim.x + threadIdx.x;
    if (k >= NIDX) return;
    int pd = i0[k] * H + i1[k];
    bool dz = (msrc[pd] == 0.0f);
#pragma unroll
    for (int c = 0; c < 3; c++) {
        float v = dz ? 0.0f : dn(ref[c * HH + pd]) * 255.0f;
        int b = min((int)v, NBINS - 1);
        o_match[c * HH + pd] = g_tab[c][b];  // duplicates write identical values
    }
}

// ---------------- kernel 5: L1 mean reduction -----------------------------
__global__ void loss_k(const float4* __restrict__ a, const float4* __restrict__ b) {
    float local = 0.0f;
    for (int i = blockIdx.x * blockDim.x + threadIdx.x; i < P4;
         i += gridDim.x * blockDim.x) {
        float4 x = a[i], y = b[i];
        local += fabsf(x.x - y.x) + fabsf(x.y - y.y) +
                 fabsf(x.z - y.z) + fabsf(x.w - y.w);
    }
#pragma unroll
    for (int off = 16; off; off >>= 1) local += __shfl_down_sync(0xFFFFFFFFu, local, off);
    __shared__ float ws[8];
    if ((threadIdx.x & 31) == 0) ws[threadIdx.x >> 5] = local;
    __syncthreads();
    if (threadIdx.x < 32) {
        float v = (threadIdx.x < (blockDim.x >> 5)) ? ws[threadIdx.x] : 0.0f;
#pragma unroll
        for (int off = 4; off; off >>= 1) v += __shfl_down_sync(0xFFFFFFFFu, v, off);
        if (threadIdx.x == 0) atomicAdd(&g_acc, (double)v);
    }
}

__global__ void fin_k(float* __restrict__ o) {
    o[0] = (float)(g_acc / (double)P);
}

// ---------------- launch -------------------------------------------------
extern "C" void kernel_launch(void* const* d_in, const int* in_sizes, int n_in,
                              void* d_out, int out_size) {
    const float* inp  = (const float*)d_in[0];
    const float* tgt  = (const float*)d_in[1];
    const float* ref  = (const float*)d_in[2];
    const float* msrc = (const float*)d_in[3];
    const float* mtar = (const float*)d_in[4];
    // d_in[5] = target_data_eye (unused by reference)
    const int* i0 = (const int*)d_in[6];
    const int* i1 = (const int*)d_in[7];
    const int* i2 = (const int*)d_in[8];
    const int* i3 = (const int*)d_in[9];
    float* out = (float*)d_out;

    ew_k<<<(P4 + 255) / 256, 256>>>((const float4*)inp, (const float4*)tgt,
                                    (const float4*)ref, (const float4*)msrc,
                                    (const float4*)mtar, (float4*)out);
    hist_k<<<(NIDX + 255) / 256, 256>>>(ref, tgt, msrc, mtar, i0, i1, i2, i3);
    tab_k<<<1, 256>>>();
    scat_k<<<(NIDX + 255) / 256, 256>>>(ref, msrc, i0, i1, out + (size_t)3 * P);
    loss_k<<<148 * 4, 256>>>((const float4*)(out + (size_t)2 * P),
                             (const float4*)(out + (size_t)3 * P));
    fin_k<<<1, 1>>>(out + (size_t)4 * P);
}

// round 3
// speedup vs baseline: 1.2221x; 1.1042x over previous
#include <cuda_runtime.h>

#define H     1024
#define HH    (H * H)
#define P     (3 * HH)
#define P4    (P / 4)
#define HH4   (HH / 4)
#define NBINS 256
#define NIDX  400000

// ---------------- device scratch (no allocation allowed) ----------------
__device__ int      g_hist[6 * NBINS];
__device__ float    g_tab[3][NBINS];      // table[b]/255 per channel
__device__ double   g_acc;
__device__ unsigned g_cnt;
__device__ unsigned g_binD[HH];           // packed bins of ref_masked  (b0|b1<<8|b2<<16)
__device__ unsigned g_binR[HH];           // packed bins of target_masked

__device__ __forceinline__ float dn(float x) {
    float v = (x + 1.0f) * 0.5f;
    return fminf(fmaxf(v, 0.0f), 1.0f);
}

__device__ __forceinline__ int binof(float v255) {  // v255 in [0,255]
    return min((int)v255, NBINS - 1);
}

// ---------------- kernel 1: elementwise transforms + bin packing ---------
// out planes: [0:P) target_masked/255, [P:2P) ref_masked/255,
//             [2P:3P) input_masked/255, [3P:4P) input_match base (= ref_masked/255)
__global__ void ew_k(const float4* __restrict__ inp, const float4* __restrict__ tgt,
                     const float4* __restrict__ ref, const float4* __restrict__ msrc,
                     const float4* __restrict__ mtar, float4* __restrict__ out) {
    if (blockIdx.x == 0) {
        for (int t = threadIdx.x; t < 6 * NBINS; t += blockDim.x) g_hist[t] = 0;
        if (threadIdx.x == 0) { g_acc = 0.0; g_cnt = 0u; }
    }
    int i = blockIdx.x * blockDim.x + threadIdx.x;   // pixel-group index [0, HH4)
    if (i >= HH4) return;
    float4 ms = msrc[i];
    float4 mt = mtar[i];
    float mu[4] = { ms.x != 0.0f ? 1.0f : 0.0f, ms.y != 0.0f ? 1.0f : 0.0f,
                    ms.z != 0.0f ? 1.0f : 0.0f, ms.w != 0.0f ? 1.0f : 0.0f };
    float tu[4] = { mt.x != 0.0f ? 1.0f : 0.0f, mt.y != 0.0f ? 1.0f : 0.0f,
                    mt.z != 0.0f ? 1.0f : 0.0f, mt.w != 0.0f ? 1.0f : 0.0f };
    unsigned pd[4] = {0, 0, 0, 0};   // packed bins, ref_masked
    unsigned pr[4] = {0, 0, 0, 0};   // packed bins, target_masked
#pragma unroll
    for (int c = 0; c < 3; c++) {
        float4 t = tgt[c * HH4 + i];
        float4 r = ref[c * HH4 + i];
        float4 in = inp[c * HH4 + i];
        float to[4] = {dn(t.x), dn(t.y), dn(t.z), dn(t.w)};
        float ro[4] = {dn(r.x), dn(r.y), dn(r.z), dn(r.w)};
        float io[4] = {fminf(fmaxf(in.x, 0.0f), 1.0f), fminf(fmaxf(in.y, 0.0f), 1.0f),
                       fminf(fmaxf(in.z, 0.0f), 1.0f), fminf(fmaxf(in.w, 0.0f), 1.0f)};
        float4 otm, orm, oim;
        float* potm = (float*)&otm; float* porm = (float*)&orm; float* poim = (float*)&oim;
#pragma unroll
        for (int j = 0; j < 4; j++) {
            float rm = ro[j] * mu[j];
            float tm = to[j] * tu[j];
            potm[j] = tm;
            porm[j] = rm;
            poim[j] = io[j] * mu[j];
            pd[j] |= (unsigned)binof(rm * 255.0f) << (8 * c);
            pr[j] |= (unsigned)binof(tm * 255.0f) << (8 * c);
        }
        out[c * HH4 + i]          = otm;
        out[P4 + c * HH4 + i]     = orm;
        out[2 * P4 + c * HH4 + i] = oim;
        out[3 * P4 + c * HH4 + i] = orm;   // scatter overwrites selected pixels
    }
    ((uint4*)g_binD)[i] = make_uint4(pd[0], pd[1], pd[2], pd[3]);
    ((uint4*)g_binR)[i] = make_uint4(pr[0], pr[1], pr[2], pr[3]);
}

// ---------------- kernel 2: privatized histograms (packed-bin gathers) ---
__global__ void hist_k(const int* __restrict__ i0, const int* __restrict__ i1,
                       const int* __restrict__ i2, const int* __restrict__ i3) {
    __shared__ int sh[6 * NBINS];
    for (int t = threadIdx.x; t < 6 * NBINS; t += blockDim.x) sh[t] = 0;
    __syncthreads();

    int k = blockIdx.x * blockDim.x + threadIdx.x;
    if (k < NIDX) {
        unsigned bd = g_binD[i0[k] * H + i1[k]];
        atomicAdd(&sh[bd & 255u], 1);
        atomicAdd(&sh[NBINS + ((bd >> 8) & 255u)], 1);
        atomicAdd(&sh[2 * NBINS + ((bd >> 16) & 255u)], 1);
        unsigned br = g_binR[i2[k] * H + i3[k]];
        atomicAdd(&sh[3 * NBINS + (br & 255u)], 1);
        atomicAdd(&sh[4 * NBINS + ((br >> 8) & 255u)], 1);
        atomicAdd(&sh[5 * NBINS + ((br >> 16) & 255u)], 1);
    }
    __syncthreads();
    for (int t = threadIdx.x; t < 6 * NBINS; t += blockDim.x) {
        int v = sh[t];
        if (v) atomicAdd(&g_hist[t], v);
    }
}

// ---------------- kernel 3: CDF + transfer table (1 block, 256 thr) ------
// Counts are integers <= 400000 < 2^24: every partial sum is exact in f32,
// so the parallel scan bit-matches JAX's sequential cumsum.
__global__ void tab_k() {
    __shared__ float cdf[6][NBINS];
    int b = threadIdx.x;  // 256 threads

#pragma unroll
    for (int c = 0; c < 6; c++) cdf[c][b] = (float)g_hist[c * NBINS + b];
    __syncthreads();

    for (int off = 1; off < NBINS; off <<= 1) {
        float v[6];
#pragma unroll
        for (int c = 0; c < 6; c++) v[c] = (b >= off) ? cdf[c][b - off] : 0.0f;
        __syncthreads();
#pragma unroll
        for (int c = 0; c < 6; c++) cdf[c][b] += v[c];
        __syncthreads();
    }

#pragma unroll
    for (int c = 0; c < 6; c++) cdf[c][b] = __fdiv_rn(cdf[c][b], (float)NIDX);
    __syncthreads();

#pragma unroll
    for (int c = 0; c < 3; c++) {
        int tab;
        if (b == NBINS - 1) {
            tab = NBINS - 1;
        } else {
            tab = b;
            float r = cdf[c][b];
            const float* cr = cdf[3 + c];
            for (int j = 0; j < NBINS - 1; j++) {
                if (r >= cr[j] && r <= cr[j + 1]) { tab = j + 1; break; }
            }
        }
        g_tab[c][b] = __fdiv_rn((float)tab, 255.0f);
    }
}

// ---------------- kernel 4: scatter matched values ------------------------
__global__ void scat_k(const int* __restrict__ i0, const int* __restrict__ i1,
                       float* __restrict__ o_match) {
    __shared__ float stab[3][NBINS];
    {
        int t = threadIdx.x;
        stab[0][t] = g_tab[0][t];
        stab[1][t] = g_tab[1][t];
        stab[2][t] = g_tab[2][t];
    }
    __syncthreads();
    int k = blockIdx.x * blockDim.x + threadIdx.x;
    if (k >= NIDX) return;
    int pd = i0[k] * H + i1[k];
    unsigned bd = g_binD[pd];
    o_match[pd]          = stab[0][bd & 255u];          // duplicates write identical values
    o_match[HH + pd]     = stab[1][(bd >> 8) & 255u];
    o_match[2 * HH + pd] = stab[2][(bd >> 16) & 255u];
}

// ---------------- kernel 5: L1 mean reduction + finalize ------------------
__global__ void loss_k(const float4* __restrict__ a, const float4* __restrict__ b,
                       float* __restrict__ o_loss) {
    float local = 0.0f;
    for (int i = blockIdx.x * blockDim.x + threadIdx.x; i < P4;
         i += gridDim.x * blockDim.x) {
        float4 x = a[i], y = b[i];
        local += fabsf(x.x - y.x) + fabsf(x.y - y.y) +
                 fabsf(x.z - y.z) + fabsf(x.w - y.w);
    }
#pragma unroll
    for (int off = 16; off; off >>= 1) local += __shfl_down_sync(0xFFFFFFFFu, local, off);
    __shared__ float ws[8];
    __shared__ bool last;
    if ((threadIdx.x & 31) == 0) ws[threadIdx.x >> 5] = local;
    __syncthreads();
    if (threadIdx.x < 32) {
        float v = (threadIdx.x < (blockDim.x >> 5)) ? ws[threadIdx.x] : 0.0f;
#pragma unroll
        for (int off = 4; off; off >>= 1) v += __shfl_down_sync(0xFFFFFFFFu, v, off);
        if (threadIdx.x == 0) {
            atomicAdd(&g_acc, (double)v);
            __threadfence();
            unsigned done = atomicAdd(&g_cnt, 1u);
            last = (done == gridDim.x - 1);
        }
    }
    __syncthreads();
    if (last && threadIdx.x == 0) {
        double total = atomicAdd(&g_acc, 0.0);   // all adds fenced-visible
        o_loss[0] = (float)(total / (double)P);
    }
}

// ---------------- launch -------------------------------------------------
extern "C" void kernel_launch(void* const* d_in, const int* in_sizes, int n_in,
                              void* d_out, int out_size) {
    const float* inp  = (const float*)d_in[0];
    const float* tgt  = (const float*)d_in[1];
    const float* ref  = (const float*)d_in[2];
    const float* msrc = (const float*)d_in[3];
    const float* mtar = (const float*)d_in[4];
    // d_in[5] = target_data_eye (unused by reference)
    const int* i0 = (const int*)d_in[6];
    const int* i1 = (const int*)d_in[7];
    const int* i2 = (const int*)d_in[8];
    const int* i3 = (const int*)d_in[9];
    float* out = (float*)d_out;

    ew_k<<<HH4 / 256, 256>>>((const float4*)inp, (const float4*)tgt,
                             (const float4*)ref, (const float4*)msrc,
                             (const float4*)mtar, (float4*)out);
    hist_k<<<(NIDX + 255) / 256, 256>>>(i0, i1, i2, i3);
    tab_k<<<1, 256>>>();
    scat_k<<<(NIDX + 255) / 256, 256>>>(i0, i1, out + (size_t)3 * P);
    loss_k<<<148 * 4, 256>>>((const float4*)(out + (size_t)2 * P),
                             (const float4*)(out + (size_t)3 * P),
                             out + (size_t)4 * P);
}